// round 17
// baseline (speedup 1.0000x reference)
#include <cuda_runtime.h>
#include <cuda_bf16.h>
#include <cuda_fp16.h>
#include <cstdint>

#define HGRID 768
#define WGRID 768
#define NMAX  200064   // 1563 * 128

// Scratch in __device__ globals (no allocation allowed).
__device__ int g_idx_map[HGRID * WGRID];
// h1 as plain fp16 rows: 128B per site (64 x fp16)
__device__ __align__(16) unsigned char g_h1b[(size_t)NMAX * 128];
// Weight fragments (fp16):
__device__ uint2 g_w1h[16 * 8 * 32];      // w1: [kc(16)][nt(8)][lane]
__device__ uint2 g_w2h[9 * 4 * 8 * 32];   // w2: [tap][kc][nt][lane]
__device__ uint2 g_w3h[4 * 4 * 8 * 32];   // w3: [cb][kc][nt][lane]

// ---------------------------------------------------------------------------
__device__ __forceinline__ int coords_is64(const int* c) { return c[1] == 0; }
__device__ __forceinline__ int load_coord(const int* c, int is64, int i) {
    return is64 ? c[2 * i] : c[i];
}
// fp16 exact split: a = hi + lo to ~2^-22
__device__ __forceinline__ void hsplit2(float a, float b, uint32_t& hi, uint32_t& lo) {
    __half ah = __float2half_rn(a);
    __half bh = __float2half_rn(b);
    float ar = a - __half2float(ah);
    float br = b - __half2float(bh);
    __half2 h; h.x = ah; h.y = bh;
    __half2 l; l.x = __float2half_rn(ar); l.y = __float2half_rn(br);
    hi = *reinterpret_cast<uint32_t*>(&h);
    lo = *reinterpret_cast<uint32_t*>(&l);
}
__device__ __forceinline__ uint32_t pack_h2(float a, float b) {
    __half2 h; h.x = __float2half_rn(a); h.y = __float2half_rn(b);
    return *reinterpret_cast<uint32_t*>(&h);
}
__device__ __forceinline__ uint32_t smem_u32(const void* p) {
    uint32_t a;
    asm("{ .reg .u64 t; cvta.to.shared.u64 t, %1; cvt.u32.u64 %0, t; }"
        : "=r"(a) : "l"(p));
    return a;
}
// L2-direct async copy (bypasses L1)
__device__ __forceinline__ void cp_async16_cg(uint32_t dst, const void* src, int srcsize) {
    asm volatile("cp.async.cg.shared.global [%0], [%1], 16, %2;"
                 :: "r"(dst), "l"(src), "r"(srcsize) : "memory");
}
#define CP_COMMIT() asm volatile("cp.async.commit_group;" ::: "memory")
#define CP_WAIT0()  asm volatile("cp.async.wait_group 0;" ::: "memory")
#define CP_WAIT1()  asm volatile("cp.async.wait_group 1;" ::: "memory")

// mma.sync m16n8k16 fp16 -> f32 accumulate
__device__ __forceinline__ void mma16816h(float c[4], const uint32_t a[4],
                                          uint32_t b0, uint32_t b1) {
    asm volatile(
        "mma.sync.aligned.m16n8k16.row.col.f32.f16.f16.f32 "
        "{%0,%1,%2,%3}, {%4,%5,%6,%7}, {%8,%9}, {%0,%1,%2,%3};"
        : "+f"(c[0]), "+f"(c[1]), "+f"(c[2]), "+f"(c[3])
        : "r"(a[0]), "r"(a[1]), "r"(a[2]), "r"(a[3]), "r"(b0), "r"(b1));
}

// ---------------------------------------------------------------------------
// util1: clear idx_map (all threads) + prep w2 fp16 fragments (first 9216)
__global__ void util1_kernel(const float* __restrict__ w2) {
    int i = blockIdx.x * blockDim.x + threadIdx.x;
    if (i < HGRID * WGRID) g_idx_map[i] = -1;
    if (i < 9 * 4 * 8 * 32) {
        int lane = i & 31, nt = (i >> 5) & 7, kc = (i >> 8) & 3, tap = i >> 10;
        int n  = nt * 8 + (lane >> 2);
        int k0 = kc * 16 + (lane & 3) * 2;
        uint32_t p0 = pack_h2(w2[tap * 4096 + k0 * 64 + n],
                              w2[tap * 4096 + (k0 + 1) * 64 + n]);
        uint32_t p1 = pack_h2(w2[tap * 4096 + (k0 + 8) * 64 + n],
                              w2[tap * 4096 + (k0 + 9) * 64 + n]);
        g_w2h[i] = make_uint2(p0, p1);
    }
}

// util2: scatter coords + prep w3 fp16 frags (i<4096) + w1 fp16 frags ([4096,8192))
__global__ void util2_kernel(const int* __restrict__ coords,
                             const float* __restrict__ w3,
                             const float* __restrict__ w1, int n) {
    int i = blockIdx.x * blockDim.x + threadIdx.x;
    if (i < n) {
        int is64 = coords_is64(coords);
        g_idx_map[load_coord(coords, is64, i)] = i;
    }
    if (i < 4 * 4 * 8 * 32) {
        int lane = i & 31, nt = (i >> 5) & 7, kc = (i >> 8) & 3, cb = i >> 10;
        int nn = cb * 64 + nt * 8 + (lane >> 2);
        int k0 = kc * 16 + (lane & 3) * 2;
        uint32_t p0 = pack_h2(w3[k0 * 256 + nn], w3[(k0 + 1) * 256 + nn]);
        uint32_t p1 = pack_h2(w3[(k0 + 8) * 256 + nn], w3[(k0 + 9) * 256 + nn]);
        g_w3h[i] = make_uint2(p0, p1);
    } else if (i < 8192) {
        int j = i - 4096;
        int lane = j & 31, nt = (j >> 5) & 7, kc = j >> 8;   // kc 0..15
        int nn = nt * 8 + (lane >> 2);
        int k0 = kc * 16 + (lane & 3) * 2;
        uint32_t p0 = pack_h2(w1[k0 * 64 + nn], w1[(k0 + 1) * 64 + nn]);
        uint32_t p1 = pack_h2(w1[(k0 + 8) * 64 + nn], w1[(k0 + 9) * 64 + nn]);
        g_w1h[j] = make_uint2(p0, p1);
    }
}

// ---------------------------------------------------------------------------
// conv1 via fp16 2-term mma (feats exact-split + rounded w1);
// OUTPUT: plain fp16 rows (128B/site).
#define LDF 144
#define FPL (128 * LDF)
#define S1_SC 0
#define S1_F  512
#define S1_B  37376                     // 2 x 4096 -> ends 45568
#define S1_TOTAL 45568

__global__ void __launch_bounds__(256, 3) conv1_mma_kernel(
    const float* __restrict__ feats,
    const float* __restrict__ s1, const float* __restrict__ b1, int n)
{
    extern __shared__ __align__(128) char dsm1[];
    float* s_s1 = (float*)(dsm1 + S1_SC);
    float* s_b1 = s_s1 + 64;
    unsigned char* sF = (unsigned char*)(dsm1 + S1_F);
    uint2* Bsm = (uint2*)(dsm1 + S1_B);

    const int tid = threadIdx.x, wid = tid >> 5, lane = tid & 31;
    const int site0 = blockIdx.x * 128;
    const int rw = wid * 16;
    const int frow = tid >> 3, fc8 = tid & 7;

    if (tid < 64) { s_s1[tid] = s1[tid]; s_b1[tid] = b1[tid]; }

    const uint32_t f_sm = smem_u32(sF);
    const uint32_t b_sm = smem_u32(Bsm);

    auto issue_ck = [&](int ck) {
        uint32_t fdst = f_sm + (ck & 1) * FPL;
#pragma unroll
        for (int g = 0; g < 4; ++g) {
            int row = frow + g * 32;
            int site = site0 + row;
            const char* src = (const char*)feats +
                (size_t)(site < n ? site : 0) * 1024 + ck * 128 + fc8 * 16;
            cp_async16_cg(fdst + row * LDF + fc8 * 16, src, site < n ? 16 : 0);
        }
        const uint2* bs = g_w1h + (size_t)ck * 512 + tid * 2;
        uint32_t bd = b_sm + (ck & 1) * 4096 + tid * 16;
        cp_async16_cg(bd, bs, 16);
        CP_COMMIT();
    };

    float acc[8][4];
#pragma unroll
    for (int t = 0; t < 8; ++t)
#pragma unroll
        for (int j = 0; j < 4; ++j) acc[t][j] = 0.f;

    issue_ck(0);

#pragma unroll 1
    for (int ck = 0; ck < 8; ++ck) {
        CP_WAIT0();
        __syncthreads();
        if (ck < 7) issue_ck(ck + 1);

        const unsigned char* fb = sF + (ck & 1) * FPL;
        const uint2* Bcur = Bsm + (ck & 1) * 512;
#pragma unroll
        for (int kh = 0; kh < 2; ++kh) {
            uint32_t ab = (uint32_t)((rw + (lane >> 2)) * LDF + kh * 64 + (lane & 3) * 8);
            float2 p00 = *(const float2*)(fb + ab);
            float2 p10 = *(const float2*)(fb + ab + 8 * LDF);
            float2 p01 = *(const float2*)(fb + ab + 32);
            float2 p11 = *(const float2*)(fb + ab + 8 * LDF + 32);
            uint32_t ah[4], al[4];
            hsplit2(p00.x, p00.y, ah[0], al[0]);
            hsplit2(p10.x, p10.y, ah[1], al[1]);
            hsplit2(p01.x, p01.y, ah[2], al[2]);
            hsplit2(p11.x, p11.y, ah[3], al[3]);
#pragma unroll
            for (int nt = 0; nt < 8; ++nt) {
                uint2 b = Bcur[kh * 256 + nt * 32 + lane];
                mma16816h(acc[nt], ah, b.x, b.y);
                mma16816h(acc[nt], al, b.x, b.y);
            }
        }
    }
    __syncthreads();

    // epilogue: bn1 + relu, round to fp16, stage 128B rows, coalesced write
    uint32_t* sh = (uint32_t*)sF;
    {
        int r0 = rw + (lane >> 2);
        int n0 = (lane & 3) * 2;
#pragma unroll
        for (int nt = 0; nt < 8; ++nt) {
            int c0 = nt * 8 + n0;
            int wc = nt * 4 + (lane & 3);
            float v0 = fmaxf(fmaf(acc[nt][0], s_s1[c0],     s_b1[c0]),     0.f);
            float v1 = fmaxf(fmaf(acc[nt][1], s_s1[c0 + 1], s_b1[c0 + 1]), 0.f);
            float v2 = fmaxf(fmaf(acc[nt][2], s_s1[c0],     s_b1[c0]),     0.f);
            float v3 = fmaxf(fmaf(acc[nt][3], s_s1[c0 + 1], s_b1[c0 + 1]), 0.f);
            sh[r0 * 32 + wc]       = pack_h2(v0, v1);
            sh[(r0 + 8) * 32 + wc] = pack_h2(v2, v3);
        }
    }
    __syncthreads();
    {
        int chunk = tid & 7, rbase = tid >> 3;
#pragma unroll
        for (int it = 0; it < 4; ++it) {
            int row = rbase + it * 32;
            uint4 v = *(const uint4*)((const char*)sh + row * 128 + chunk * 16);
            *(uint4*)(g_h1b + (size_t)(site0 + row) * 128 + chunk * 16) = v;
        }
    }
}

// ---------------------------------------------------------------------------
// FUSED conv2 + conv3. conv2: pure fp16, 3-STAGE cp.async pipeline (prefetch
// distance 2 taps); conv3: pure fp16. 85.5KB smem -> 2 CTAs/SM.
#define APL 18432                       // A plane buffer: 128 rows * 144B
#define LDP 144
#define SM_SC    0                      // 2560
#define SM_NBR   2560                   // 4608 -> ends 7168
#define SM_A     7680                   // 3 * APL = 55296 -> ends 62976
#define SM_B     62976                  // 3 * 8192 = 24576 -> ends 87552
#define SM_TOTAL 87552

__global__ void __launch_bounds__(256) conv23_kernel(
    const int* __restrict__ coords,
    const float* __restrict__ s2, const float* __restrict__ b2,
    const float* __restrict__ feats,
    const float* __restrict__ s3, const float* __restrict__ b3,
    float* __restrict__ out, int n)
{
    extern __shared__ __align__(128) char dsm[];
    float* s_s2 = (float*)(dsm + SM_SC);
    float* s_b2 = s_s2 + 64;
    float* s_s3 = s_b2 + 64;
    float* s_b3 = s_s3 + 256;
    int*  s_nbr = (int*)(dsm + SM_NBR);
    unsigned char* Abuf = (unsigned char*)(dsm + SM_A);
    uint2* Bh2 = (uint2*)(dsm + SM_B);

    const int tid = threadIdx.x, wid = tid >> 5, lane = tid & 31;
    const int site0 = blockIdx.x * 128;
    const int rw = wid * 16;

    // gather mapping: 8 lanes per 128B h1 row; 4 rows per iter
    const int sub4  = lane >> 3;
    const int boff8 = (lane & 7) * 16;
    // epilogue mapping: 16 lanes per 256B f32 row
    const int sub  = lane >> 4;
    const int boff = (lane & 15) * 16;

    if (tid < 64) { s_s2[tid] = s2[tid]; s_b2[tid] = b2[tid]; }
    s_s3[tid] = s3[tid]; s_b3[tid] = b3[tid];
    if (tid < 128) {
#pragma unroll
        for (int t = 0; t < 9; ++t) s_nbr[t * 128 + tid] = -1;
        int site = site0 + tid;
        if (site < n) {
            int is64 = coords_is64(coords);
            int c = load_coord(coords, is64, site);
            int y = c / WGRID, x = c % WGRID;
#pragma unroll
            for (int t = 0; t < 9; ++t) {
                int ny = y + t / 3 - 1, nx = x + t % 3 - 1;
                if (ny >= 0 && ny < HGRID && nx >= 0 && nx < WGRID)
                    s_nbr[t * 128 + tid] = g_idx_map[ny * WGRID + nx];
            }
        }
    }
    __syncthreads();

    float acc[8][4];
#pragma unroll
    for (int t = 0; t < 8; ++t)
#pragma unroll
        for (int j = 0; j < 4; ++j) acc[t][j] = 0.f;

    const uint32_t a_sm = smem_u32(Abuf);
    const uint32_t b_sm = smem_u32(Bh2);

    auto issue_tap = [&](int t) {
        int slot = t % 3;
        uint32_t abase = a_sm + slot * APL + boff8;
#pragma unroll
        for (int g = 0; g < 4; ++g) {
            int row = rw + g * 4 + sub4;
            int nb = s_nbr[t * 128 + row];
            const unsigned char* src = g_h1b + (size_t)(nb < 0 ? 0 : nb) * 128 + boff8;
            cp_async16_cg(abase + row * LDP, src, nb >= 0 ? 16 : 0);
        }
        const uint2* bs = g_w2h + (size_t)t * 1024 + tid * 4;
        uint32_t bd = b_sm + slot * 8192 + tid * 32;
        cp_async16_cg(bd, bs, 16);
        cp_async16_cg(bd + 16, bs + 2, 16);
        CP_COMMIT();
    };

    issue_tap(0);
    issue_tap(1);

    // -------- conv2: 9-tap, pure fp16, 3-stage pipeline -------------------
#pragma unroll 1
    for (int tap = 0; tap < 9; ++tap) {
        if (tap < 8) CP_WAIT1(); else CP_WAIT0();   // tap's group landed
        __syncthreads();             // all warps done reading buf (tap-1)%3
        if (tap + 2 <= 8) issue_tap(tap + 2);   // slot (tap+2)%3 == (tap-1)%3

        const unsigned char* wbase = Abuf + (tap % 3) * APL;
        const uint2* Bcur = Bh2 + (tap % 3) * 1024;
#pragma unroll
        for (int kc = 0; kc < 4; ++kc) {
            uint32_t ab = (uint32_t)((rw + (lane >> 2)) * LDP + kc * 32 + (lane & 3) * 4);
            uint32_t ah[4];
            ah[0] = *(const uint32_t*)(wbase + ab);
            ah[1] = *(const uint32_t*)(wbase + ab + 8 * LDP);
            ah[2] = *(const uint32_t*)(wbase + ab + 16);
            ah[3] = *(const uint32_t*)(wbase + ab + 8 * LDP + 16);
#pragma unroll
            for (int nt = 0; nt < 8; ++nt) {
                uint2 b = Bcur[kc * 256 + nt * 32 + lane];
                mma16816h(acc[nt], ah, b.x, b.y);
            }
        }
    }
    __syncthreads();   // all warps finish MMA(tap 8) before buffer reuse

    // --- bn2 + relu in registers; ROUND to fp16 -> conv3 A-frags ----------
    uint32_t fh[4][4];
    {
        const int n0 = (lane & 3) * 2;
#pragma unroll
        for (int kc = 0; kc < 4; ++kc) {
#pragma unroll
            for (int q = 0; q < 2; ++q) {
                int nt = 2 * kc + q;
                int c0 = nt * 8 + n0;
                float v0 = fmaxf(fmaf(acc[nt][0], s_s2[c0],     s_b2[c0]),     0.f);
                float v1 = fmaxf(fmaf(acc[nt][1], s_s2[c0 + 1], s_b2[c0 + 1]), 0.f);
                float v2 = fmaxf(fmaf(acc[nt][2], s_s2[c0],     s_b2[c0]),     0.f);
                float v3 = fmaxf(fmaf(acc[nt][3], s_s2[c0 + 1], s_b2[c0 + 1]), 0.f);
                fh[kc][2 * q]     = pack_h2(v0, v1);
                fh[kc][2 * q + 1] = pack_h2(v2, v3);
            }
        }
    }

    // ---------------- conv3: pure fp16, 4 column blocks -------------------
    float* stg = (float*)Abuf;   // 128 x 64 f32 staging = 32KB (fits 3*APL)
    {   // preload cb=0 B fragments into slot 0
        const uint2* bs = g_w3h + tid * 4;
#pragma unroll
        for (int q = 0; q < 4; ++q) Bh2[tid * 4 + q] = bs[q];
    }
    __syncthreads();

#pragma unroll 1
    for (int cb = 0; cb < 4; ++cb) {
        float acc2[8][4];
#pragma unroll
        for (int t = 0; t < 8; ++t)
#pragma unroll
            for (int j = 0; j < 4; ++j) acc2[t][j] = 0.f;

#pragma unroll
        for (int kc = 0; kc < 4; ++kc) {
#pragma unroll
            for (int nt = 0; nt < 8; ++nt) {
                uint2 b = Bh2[kc * 256 + nt * 32 + lane];
                mma16816h(acc2[nt], fh[kc], b.x, b.y);
            }
        }
        __syncthreads();   // B reads done; stg free (prev write-out done)
        {
            int r0 = rw + (lane >> 2);
            int n0 = (lane & 3) * 2;
#pragma unroll
            for (int nt = 0; nt < 8; ++nt) {
                int c  = nt * 8 + n0;
                int cg = cb * 64 + c;
                stg[r0 * 64 + c]           = fmaf(acc2[nt][0], s_s3[cg],     s_b3[cg]);
                stg[r0 * 64 + c + 1]       = fmaf(acc2[nt][1], s_s3[cg + 1], s_b3[cg + 1]);
                stg[(r0 + 8) * 64 + c]     = fmaf(acc2[nt][2], s_s3[cg],     s_b3[cg]);
                stg[(r0 + 8) * 64 + c + 1] = fmaf(acc2[nt][3], s_s3[cg + 1], s_b3[cg + 1]);
            }
        }
        if (cb < 3) {   // stage next cb's B fragments
            const uint2* bs = g_w3h + (size_t)(cb + 1) * 1024 + tid * 4;
#pragma unroll
            for (int q = 0; q < 4; ++q) Bh2[tid * 4 + q] = bs[q];
        }
        __syncthreads();   // stg + next B visible
        {   // coalesced residual+relu+write: 16 lanes per 256B row
#pragma unroll
            for (int g = 0; g < 8; ++g) {
                int row = rw + g * 2 + sub;
                int site = site0 + row;
                if (site < n) {
                    float4 a = *(const float4*)((const char*)stg + row * 256 + boff);
                    float4 b = *(const float4*)((const char*)feats +
                                                (size_t)site * 1024 + cb * 256 + boff);
                    float4 o;
                    o.x = fmaxf(a.x + b.x, 0.f);
                    o.y = fmaxf(a.y + b.y, 0.f);
                    o.z = fmaxf(a.z + b.z, 0.f);
                    o.w = fmaxf(a.w + b.w, 0.f);
                    *(float4*)((char*)out + (size_t)site * 1024 + cb * 256 + boff) = o;
                }
            }
        }
    }
}

// ---------------------------------------------------------------------------
extern "C" void kernel_launch(void* const* d_in, const int* in_sizes, int n_in,
                              void* d_out, int out_size) {
    const float* feats  = (const float*)d_in[0];
    const int*   coords = (const int*)d_in[1];
    const float* w1     = (const float*)d_in[2];
    const float* w2     = (const float*)d_in[3];
    const float* w3     = (const float*)d_in[4];
    const float* s1     = (const float*)d_in[5];
    const float* b1     = (const float*)d_in[6];
    const float* s2     = (const float*)d_in[7];
    const float* b2     = (const float*)d_in[8];
    const float* s3     = (const float*)d_in[9];
    const float* b3     = (const float*)d_in[10];
    float* out = (float*)d_out;

    const int n = in_sizes[0] / 256;
    const int tiles = (n + 127) / 128;

    cudaFuncSetAttribute(conv1_mma_kernel,
                         cudaFuncAttributeMaxDynamicSharedMemorySize, S1_TOTAL);
    cudaFuncSetAttribute(conv23_kernel,
                         cudaFuncAttributeMaxDynamicSharedMemorySize, SM_TOTAL);

    // 4 launches; conv23 is launch #4 so ncu (-s/-c window) captures it.
    util1_kernel<<<(HGRID * WGRID + 255) / 256, 256>>>(w2);                   // #1
    util2_kernel<<<(max(n, 8192) + 255) / 256, 256>>>(coords, w3, w1, n);     // #2
    conv1_mma_kernel<<<tiles, 256, S1_TOTAL>>>(feats, s1, b1, n);             // #3
    conv23_kernel<<<tiles, 256, SM_TOTAL>>>(coords, s2, b2, feats, s3, b3, out, n);  // #4
}